// round 12
// baseline (speedup 1.0000x reference)
#include <cuda_runtime.h>

#define B 64
#define PAST 128
#define FUTURE 64
#define NB 192
#define N1 (B*PAST)     // 8192
#define N2 (B*FUTURE)   // 4096
#define E1 (N1*16)      // 131072
#define E2 (N2*16)      // 65536
#define F 51
#define FM1 50
#define HEADS 4
#define CAP 128

// ---------------- scratch (device globals; only ever addressed in device code) ----------------
__device__ float g_xf1[N1*F];
__device__ float g_xf2[N2*F];
__device__ float g_h1[N1*200];
__device__ float g_as1[N1*HEADS], g_ad1[N1*HEADS];
__device__ float g_x1[N1*FM1];
__device__ float g_u[N1*64], g_nu[N1];
__device__ float g_v[N2*64], g_nv[N2];
__device__ float g_tmp[N2];
__device__ float g_h2[N2*HEADS], g_as2[N2*HEADS], g_ad2[N2*HEADS];
__device__ int   g_cnt1[N1], g_cnt2[N2];
__device__ int   g_list1[N1*CAP], g_list2[N2*CAP];

__device__ __forceinline__ float lrelu(float e){ return e > 0.f ? e : 0.2f*e; }

// ---------------- kernels ----------------
__global__ void k_zero(){
    int i = blockIdx.x*blockDim.x + threadIdx.x;
    if (i < N1) g_cnt1[i] = 0;
    if (i < N2) g_cnt2[i] = 0;
}

// per-node: gather embeddings -> x row; h = x @ lin [200]; a_src/a_dst per head
__global__ void k_pre1(const int* __restrict__ cat, const float* __restrict__ num,
                       const float* __restrict__ emb0, const float* __restrict__ emb1,
                       const float* __restrict__ emb2, const float* __restrict__ lin,
                       const float* __restrict__ asrc, const float* __restrict__ adst)
{
    __shared__ float sx[F];
    __shared__ float ss[HEADS], sd[HEADS];
    int n = blockIdx.x, t = threadIdx.x;
    if (t < HEADS) { ss[t] = 0.f; sd[t] = 0.f; }
    if (t < F) {
        float v;
        if      (t < 16) v = emb0[cat[n*3+0]*16 + t];
        else if (t < 24) v = emb1[cat[n*3+1]*8  + (t-16)];
        else if (t < 48) v = emb2[cat[n*3+2]*24 + (t-24)];
        else             v = num[n*3 + (t-48)];
        sx[t] = v;
        g_xf1[n*F + t] = v;
    }
    __syncthreads();
    for (int j = t; j < 200; j += 64) {
        float h = 0.f;
        #pragma unroll
        for (int k = 0; k < F; k++) h += sx[k]*lin[k*200 + j];
        g_h1[n*200 + j] = h;
        int hd = j/FM1, c = j - hd*FM1;
        atomicAdd(&ss[hd], h*asrc[hd*FM1 + c]);
        atomicAdd(&sd[hd], h*adst[hd*FM1 + c]);
    }
    __syncthreads();
    if (t < HEADS) { g_as1[n*HEADS+t] = ss[t]; g_ad1[n*HEADS+t] = sd[t]; }
}

// per-node (graph2): features; v = x[:50] @ W; nv = |v|^2
__global__ void k_pre2(const int* __restrict__ cat, const float* __restrict__ num,
                       const float* __restrict__ emb0, const float* __restrict__ emb1,
                       const float* __restrict__ emb2, const float* __restrict__ W)
{
    __shared__ float sx[F];
    __shared__ float red[2];
    int n = blockIdx.x, t = threadIdx.x;
    if (t < F) {
        float v;
        if      (t < 16) v = emb0[cat[n*3+0]*16 + t];
        else if (t < 24) v = emb1[cat[n*3+1]*8  + (t-16)];
        else if (t < 48) v = emb2[cat[n*3+2]*24 + (t-24)];
        else             v = num[n*3 + (t-48)];
        sx[t] = v;
        g_xf2[n*F + t] = v;
    }
    __syncthreads();
    float u = 0.f;
    #pragma unroll
    for (int k = 0; k < FM1; k++) u += sx[k]*W[k*64 + t];
    g_v[n*64 + t] = u;
    float q = u*u;
    #pragma unroll
    for (int o = 16; o; o >>= 1) q += __shfl_down_sync(0xffffffffu, q, o);
    if ((t & 31) == 0) red[t>>5] = q;
    __syncthreads();
    if (t == 0) g_nv[n] = red[0] + red[1];
}

// CSR-less scatter. NOTE: g_cnt*/g_list* are touched ONLY inside device code —
// passing a __device__ symbol as a host-side kernel argument silently resolves
// to the host shadow address (ATS on GB300 makes the GPU write host RAM with no
// fault) — that was the single bug behind rounds 1-11.
__global__ void k_scatter1(const int* __restrict__ e)
{
    int i = blockIdx.x*blockDim.x + threadIdx.x;
    if (i >= E1) return;
    int src = e[i], dst = e[E1 + i];
    int pos = atomicAdd(&g_cnt1[dst], 1);
    if (pos < CAP) g_list1[dst*CAP + pos] = src;
}
__global__ void k_scatter2(const int* __restrict__ e)
{
    int i = blockIdx.x*blockDim.x + threadIdx.x;
    if (i >= E2) return;
    int src = e[i], dst = e[E2 + i];
    int pos = atomicAdd(&g_cnt2[dst], 1);
    if (pos < CAP) g_list2[dst*CAP + pos] = src;
}

// GAT1 gather: block per dst node, warp per head, 2 channels per lane.
__global__ void k_gat1()
{
    __shared__ float sh[HEADS][FM1];
    int n = blockIdx.x, t = threadIdx.x;
    int w = t >> 5, lane = t & 31;
    int c0 = lane, c1 = lane + 32;
    float ad = g_ad1[n*HEADS + w];
    float e0 = g_as1[n*HEADS + w] + ad;
    float wt = __expf(lrelu(e0));
    float s  = wt;
    float a0 = wt * g_h1[n*200 + w*FM1 + c0];
    float a1 = (c1 < FM1) ? wt * g_h1[n*200 + w*FM1 + c1] : 0.f;
    int deg = min(g_cnt1[n], CAP);
    const int* lst = &g_list1[n*CAP];
    for (int i = 0; i < deg; i++) {
        int src = lst[i];
        float e = g_as1[src*HEADS + w] + ad;
        float x = __expf(lrelu(e));
        s += x;
        a0 += x * g_h1[src*200 + w*FM1 + c0];
        if (c1 < FM1) a1 += x * g_h1[src*200 + w*FM1 + c1];
    }
    float inv = 1.f / (s + 1e-16f);
    sh[w][c0] = a0 * inv;
    if (c1 < FM1) sh[w][c1] = a1 * inv;
    __syncthreads();
    if (t < FM1)
        g_x1[n*FM1 + t] = 0.25f*(sh[0][t] + sh[1][t] + sh[2][t] + sh[3][t]);
}

// u = (x1 + bias) @ W ; nu = |u|^2
__global__ void k_u(const float* __restrict__ bias, const float* __restrict__ W)
{
    __shared__ float sx[FM1];
    __shared__ float red[2];
    int n = blockIdx.x, t = threadIdx.x;
    if (t < FM1) sx[t] = g_x1[n*FM1 + t] + bias[t];
    __syncthreads();
    float u = 0.f;
    #pragma unroll
    for (int k = 0; k < FM1; k++) u += sx[k]*W[k*64 + t];
    g_u[n*64 + t] = u;
    float q = u*u;
    #pragma unroll
    for (int o = 16; o; o >>= 1) q += __shfl_down_sync(0xffffffffu, q, o);
    if ((t & 31) == 0) red[t>>5] = q;
    __syncthreads();
    if (t == 0) g_nu[n] = red[0] + red[1];
}

// per (b, group of 8 f): L[f][p] = 2 u.v - |u|^2 - |v|^2 (= -||u-v||^2 = -0.5 diff M diff),
// mask by A, softmax over p, dot with y_past.
__global__ void k_alpha(const int* __restrict__ A)
{
    __shared__ float sv[8*64];
    __shared__ float sy[PAST];
    __shared__ float snv[8];
    __shared__ float sL[8][PAST];
    int b = blockIdx.x >> 3;
    int fb = (blockIdx.x & 7) * 8;
    int p = threadIdx.x;               // 128 threads
    const float* vbase = g_v + (b*FUTURE + fb)*64;
    for (int i = p; i < 512; i += 128) sv[i] = vbase[i];
    sy[p] = g_xf1[(b*PAST + p)*F + (F-1)];
    if (p < 8) snv[p] = g_nv[b*FUTURE + fb + p];
    __syncthreads();
    float acc[8];
    #pragma unroll
    for (int f = 0; f < 8; f++) acc[f] = 0.f;
    const float4* up4 = (const float4*)(g_u + (b*PAST + p)*64);
    #pragma unroll
    for (int kc = 0; kc < 16; kc++) {
        float4 uq = up4[kc];
        #pragma unroll
        for (int f = 0; f < 8; f++) {
            acc[f] += uq.x*sv[f*64 + kc*4 + 0] + uq.y*sv[f*64 + kc*4 + 1]
                    + uq.z*sv[f*64 + kc*4 + 2] + uq.w*sv[f*64 + kc*4 + 3];
        }
    }
    float nup = g_nu[b*PAST + p];
    const int* Arow = A + p*NB + PAST + fb;
    #pragma unroll
    for (int f = 0; f < 8; f++) {
        float L = 2.f*acc[f] - nup - snv[f];
        if (Arow[f] == 0) L = -1e30f;
        sL[f][p] = L;
    }
    __syncthreads();
    int w = p >> 5, lane = p & 31;
    for (int f = w; f < 8; f += 4) {
        float v0 = sL[f][lane], v1 = sL[f][lane+32], v2 = sL[f][lane+64], v3 = sL[f][lane+96];
        float m = fmaxf(fmaxf(v0, v1), fmaxf(v2, v3));
        #pragma unroll
        for (int o = 16; o; o >>= 1) m = fmaxf(m, __shfl_xor_sync(0xffffffffu, m, o));
        float e0 = __expf(v0 - m), e1 = __expf(v1 - m), e2 = __expf(v2 - m), e3 = __expf(v3 - m);
        float s = e0 + e1 + e2 + e3;
        float a = e0*sy[lane] + e1*sy[lane+32] + e2*sy[lane+64] + e3*sy[lane+96];
        #pragma unroll
        for (int o = 16; o; o >>= 1) {
            s += __shfl_xor_sync(0xffffffffu, s, o);
            a += __shfl_xor_sync(0xffffffffu, a, o);
        }
        if (lane == 0) g_tmp[b*FUTURE + fb + f] = a / s;
    }
}

// h2 = [x2[:50], tmp] @ g2_lin; attention pieces per head (out_ch = 1)
__global__ void k_h2(const float* __restrict__ lin, const float* __restrict__ asrc,
                     const float* __restrict__ adst)
{
    int n = blockIdx.x*blockDim.x + threadIdx.x;
    if (n >= N2) return;
    float acc[HEADS] = {0.f, 0.f, 0.f, 0.f};
    #pragma unroll 4
    for (int k = 0; k < F; k++) {
        float xv = (k < FM1) ? g_xf2[n*F + k] : g_tmp[n];
        #pragma unroll
        for (int h = 0; h < HEADS; h++) acc[h] += xv*lin[k*HEADS + h];
    }
    #pragma unroll
    for (int h = 0; h < HEADS; h++) {
        g_h2[n*HEADS + h]  = acc[h];
        g_as2[n*HEADS + h] = acc[h]*asrc[h];
        g_ad2[n*HEADS + h] = acc[h]*adst[h];
    }
}

// GAT2 gather: warp per dst node, scalar channel, mean over heads -> output
__global__ void k_gat2(float* __restrict__ out, const float* __restrict__ g2b)
{
    int wid = (blockIdx.x*blockDim.x + threadIdx.x) >> 5;
    int lane = threadIdx.x & 31;
    if (wid >= N2) return;
    int n = wid;
    int deg = min(g_cnt2[n], CAP);
    const int* lst = &g_list2[n*CAP];
    float osum = 0.f;
    #pragma unroll
    for (int h = 0; h < HEADS; h++) {
        float ad = g_ad2[n*HEADS + h];
        float s = 0.f, a = 0.f;
        for (int i = lane; i < deg; i += 32) {
            int src = lst[i];
            float e = g_as2[src*HEADS + h] + ad;
            float x = __expf(lrelu(e));
            s += x; a += x*g_h2[src*HEADS + h];
        }
        #pragma unroll
        for (int o = 16; o; o >>= 1) {
            s += __shfl_xor_sync(0xffffffffu, s, o);
            a += __shfl_xor_sync(0xffffffffu, a, o);
        }
        if (lane == 0) {
            float e = g_as2[n*HEADS + h] + ad;
            float x = __expf(lrelu(e));
            s += x; a += x*g_h2[n*HEADS + h];
            osum += a / (s + 1e-16f);
        }
    }
    if (lane == 0) out[n] = 0.25f*osum + g2b[0];
}

// ---------------- launcher (inputs confirmed: insertion order, element counts, int32) ----------------
extern "C" void kernel_launch(void* const* d_in, const int* in_sizes, int n_in,
                              void* d_out, int out_size)
{
    const int*   cat1   = (const int*)  d_in[0];
    const float* num1   = (const float*)d_in[1];
    const int*   cat2   = (const int*)  d_in[2];
    const float* num2   = (const float*)d_in[3];
    const int*   e1     = (const int*)  d_in[4];
    const int*   e2     = (const int*)  d_in[5];
    const int*   A      = (const int*)  d_in[6];
    const float* emb0   = (const float*)d_in[7];
    const float* emb1   = (const float*)d_in[8];
    const float* emb2   = (const float*)d_in[9];
    const float* g1_lin = (const float*)d_in[10];
    const float* g1_as  = (const float*)d_in[11];
    const float* g1_ad  = (const float*)d_in[12];
    const float* g1_b   = (const float*)d_in[13];
    const float* g2_lin = (const float*)d_in[14];
    const float* g2_as  = (const float*)d_in[15];
    const float* g2_ad  = (const float*)d_in[16];
    const float* g2_b   = (const float*)d_in[17];
    const float* W      = (const float*)d_in[18];
    float* out = (float*)d_out;

    k_zero<<<32, 256>>>();
    k_pre1<<<N1, 64>>>(cat1, num1, emb0, emb1, emb2, g1_lin, g1_as, g1_ad);
    k_pre2<<<N2, 64>>>(cat2, num2, emb0, emb1, emb2, W);
    k_scatter1<<<(E1+255)/256, 256>>>(e1);
    k_scatter2<<<(E2+255)/256, 256>>>(e2);
    k_gat1<<<N1, 128>>>();
    k_u<<<N1, 64>>>(g1_b, W);
    k_alpha<<<B*8, 128>>>(A);
    k_h2<<<(N2+127)/128, 128>>>(g2_lin, g2_as, g2_ad);
    k_gat2<<<N2/8, 256>>>(out, g2_b);
}

// round 16
// speedup vs baseline: 1.7396x; 1.7396x over previous
#include <cuda_runtime.h>

#define B 64
#define PAST 128
#define FUTURE 64
#define NB 192
#define N1 (B*PAST)     // 8192
#define N2 (B*FUTURE)   // 4096
#define E1 (N1*16)      // 131072
#define E2 (N2*16)      // 65536
#define F 51
#define FM1 50
#define HEADS 4
#define CAP 128

// ---------------- scratch (addressed ONLY in device code) ----------------
__device__ float g_y1[N1];           // last feature column of graph-1 nodes
__device__ float g_xf2[N2*F];
__device__ float g_h1[N1*200];
__device__ float g_as1[N1*HEADS], g_ad1[N1*HEADS];
__device__ float g_x1[N1*FM1];
__device__ float g_u[N1*64], g_nu[N1];
__device__ float g_v[N2*64], g_nv[N2];
__device__ float g_tmp[N2];
__device__ float g_h2[N2*HEADS], g_as2[N2*HEADS], g_ad2[N2*HEADS];
__device__ int   g_cnt1[N1], g_cnt2[N2];
__device__ int   g_list1[N1*CAP], g_list2[N2*CAP];

__device__ __forceinline__ float lrelu(float e){ return e > 0.f ? e : 0.2f*e; }

// ---------------- pre1: 16 nodes/block; h = x@lin; as/ad; y; zero cnt1 ----------------
__global__ void k_pre1(const int* __restrict__ cat, const float* __restrict__ num,
                       const float* __restrict__ emb0, const float* __restrict__ emb1,
                       const float* __restrict__ emb2, const float* __restrict__ lin,
                       const float* __restrict__ asrc, const float* __restrict__ adst)
{
    __shared__ float sxT[F][16];       // transposed features
    __shared__ float satt[2][200];
    __shared__ float sh[16][200];
    int t = threadIdx.x;               // 256 threads
    int base = blockIdx.x * 16;
    if (t < 200) { satt[0][t] = asrc[t]; satt[1][t] = adst[t]; }
    if (t < 16) g_cnt1[base + t] = 0;
    for (int i = t; i < 16*F; i += 256) {
        int n = i / F, c = i - n*F;
        int gn = base + n;
        float v;
        if      (c < 16) v = emb0[cat[gn*3+0]*16 + c];
        else if (c < 24) v = emb1[cat[gn*3+1]*8  + (c-16)];
        else if (c < 48) v = emb2[cat[gn*3+2]*24 + (c-24)];
        else             v = num[gn*3 + (c-48)];
        sxT[c][n] = v;
        if (c == F-1) g_y1[gn] = v;
    }
    __syncthreads();
    if (t < 200) {
        int cg = t % 50, ng = t / 50;          // col-group, node-group
        int col = cg * 4, n0 = ng * 4;
        float4 acc0 = {0,0,0,0}, acc1 = {0,0,0,0}, acc2 = {0,0,0,0}, acc3 = {0,0,0,0};
        #pragma unroll
        for (int k = 0; k < F; k++) {
            float4 lv = *(const float4*)(lin + k*200 + col);
            float4 xv = *(const float4*)&sxT[k][n0];
            acc0.x += xv.x*lv.x; acc0.y += xv.x*lv.y; acc0.z += xv.x*lv.z; acc0.w += xv.x*lv.w;
            acc1.x += xv.y*lv.x; acc1.y += xv.y*lv.y; acc1.z += xv.y*lv.z; acc1.w += xv.y*lv.w;
            acc2.x += xv.z*lv.x; acc2.y += xv.z*lv.y; acc2.z += xv.z*lv.z; acc2.w += xv.z*lv.w;
            acc3.x += xv.w*lv.x; acc3.y += xv.w*lv.y; acc3.z += xv.w*lv.z; acc3.w += xv.w*lv.w;
        }
        *(float4*)&sh[n0+0][col] = acc0;
        *(float4*)&sh[n0+1][col] = acc1;
        *(float4*)&sh[n0+2][col] = acc2;
        *(float4*)&sh[n0+3][col] = acc3;
        *(float4*)(g_h1 + (base+n0+0)*200 + col) = acc0;
        *(float4*)(g_h1 + (base+n0+1)*200 + col) = acc1;
        *(float4*)(g_h1 + (base+n0+2)*200 + col) = acc2;
        *(float4*)(g_h1 + (base+n0+3)*200 + col) = acc3;
    }
    __syncthreads();
    if (t < 64) {
        int n = t >> 2, hd = t & 3;
        float a = 0.f, d = 0.f;
        #pragma unroll
        for (int c = 0; c < FM1; c++) {
            float h = sh[n][hd*FM1 + c];
            a += h * satt[0][hd*FM1 + c];
            d += h * satt[1][hd*FM1 + c];
        }
        g_as1[(base+n)*4 + hd] = a;
        g_ad1[(base+n)*4 + hd] = d;
    }
}

// ---------------- pre2: 16 nodes/block; xf2; v = x@W; nv; zero cnt2 ----------------
__global__ void k_pre2(const int* __restrict__ cat, const float* __restrict__ num,
                       const float* __restrict__ emb0, const float* __restrict__ emb1,
                       const float* __restrict__ emb2, const float* __restrict__ W)
{
    __shared__ float sxT[F][16];
    int t = threadIdx.x;               // 256 threads
    int base = blockIdx.x * 16;
    if (t < 16) g_cnt2[base + t] = 0;
    for (int i = t; i < 16*F; i += 256) {
        int n = i / F, c = i - n*F;
        int gn = base + n;
        float v;
        if      (c < 16) v = emb0[cat[gn*3+0]*16 + c];
        else if (c < 24) v = emb1[cat[gn*3+1]*8  + (c-16)];
        else if (c < 48) v = emb2[cat[gn*3+2]*24 + (c-24)];
        else             v = num[gn*3 + (c-48)];
        sxT[c][n] = v;
        g_xf2[gn*F + c] = v;
    }
    __syncthreads();
    int n = t / 16, cg = t % 16, col = cg * 4;
    float4 acc = {0,0,0,0};
    #pragma unroll
    for (int k = 0; k < FM1; k++) {
        float4 wv = *(const float4*)(W + k*64 + col);
        float xv = sxT[k][n];
        acc.x += xv*wv.x; acc.y += xv*wv.y; acc.z += xv*wv.z; acc.w += xv*wv.w;
    }
    *(float4*)(g_v + (base+n)*64 + col) = acc;
    float q = acc.x*acc.x + acc.y*acc.y + acc.z*acc.z + acc.w*acc.w;
    #pragma unroll
    for (int o = 8; o; o >>= 1) q += __shfl_down_sync(0xffffffffu, q, o, 16);
    if (cg == 0) g_nv[base+n] = q;
}

// ---------------- combined edge scatter, 4 edges/thread ----------------
__global__ void k_scatter(const int* __restrict__ e1, const int* __restrict__ e2)
{
    int i = blockIdx.x*blockDim.x + threadIdx.x;
    if (i < E1/4) {
        int4 s = ((const int4*)e1)[i];
        int4 d = ((const int4*)(e1 + E1))[i];
        int p;
        p = atomicAdd(&g_cnt1[d.x], 1); if (p < CAP) g_list1[d.x*CAP + p] = s.x;
        p = atomicAdd(&g_cnt1[d.y], 1); if (p < CAP) g_list1[d.y*CAP + p] = s.y;
        p = atomicAdd(&g_cnt1[d.z], 1); if (p < CAP) g_list1[d.z*CAP + p] = s.z;
        p = atomicAdd(&g_cnt1[d.w], 1); if (p < CAP) g_list1[d.w*CAP + p] = s.w;
    } else if (i < E1/4 + E2/4) {
        int j = i - E1/4;
        int4 s = ((const int4*)e2)[j];
        int4 d = ((const int4*)(e2 + E2))[j];
        int p;
        p = atomicAdd(&g_cnt2[d.x], 1); if (p < CAP) g_list2[d.x*CAP + p] = s.x;
        p = atomicAdd(&g_cnt2[d.y], 1); if (p < CAP) g_list2[d.y*CAP + p] = s.y;
        p = atomicAdd(&g_cnt2[d.z], 1); if (p < CAP) g_list2[d.z*CAP + p] = s.z;
        p = atomicAdd(&g_cnt2[d.w], 1); if (p < CAP) g_list2[d.w*CAP + p] = s.w;
    }
}

// ---------------- GAT1 gather: block/node, warp/head ----------------
__global__ void k_gat1()
{
    __shared__ float sh[HEADS][FM1];
    int n = blockIdx.x, t = threadIdx.x;
    int w = t >> 5, lane = t & 31;
    int c0 = lane, c1 = lane + 32;
    float ad = g_ad1[n*HEADS + w];
    float e0 = g_as1[n*HEADS + w] + ad;
    float wt = __expf(lrelu(e0));
    float s  = wt;
    float a0 = wt * g_h1[n*200 + w*FM1 + c0];
    float a1 = (c1 < FM1) ? wt * g_h1[n*200 + w*FM1 + c1] : 0.f;
    int deg = min(g_cnt1[n], CAP);
    const int* lst = &g_list1[n*CAP];
    for (int i = 0; i < deg; i++) {
        int src = lst[i];
        float e = g_as1[src*HEADS + w] + ad;
        float x = __expf(lrelu(e));
        s += x;
        a0 += x * g_h1[src*200 + w*FM1 + c0];
        if (c1 < FM1) a1 += x * g_h1[src*200 + w*FM1 + c1];
    }
    float inv = 1.f / (s + 1e-16f);
    sh[w][c0] = a0 * inv;
    if (c1 < FM1) sh[w][c1] = a1 * inv;
    __syncthreads();
    if (t < FM1)
        g_x1[n*FM1 + t] = 0.25f*(sh[0][t] + sh[1][t] + sh[2][t] + sh[3][t]);
}

// ---------------- u = (x1 + bias) @ W; nu. 32 nodes/block ----------------
__global__ void k_u(const float* __restrict__ bias, const float* __restrict__ W)
{
    __shared__ float sxT[FM1][32];
    int t = threadIdx.x;               // 256 threads
    int base = blockIdx.x * 32;
    for (int i = t; i < 32*FM1; i += 256) {
        int n = i / FM1, c = i - n*FM1;
        sxT[c][n] = g_x1[(base+n)*FM1 + c] + bias[c];
    }
    __syncthreads();
    int ng = t / 16, cg = t % 16, col = cg * 4, n0 = ng * 2;
    float4 a0 = {0,0,0,0}, a1 = {0,0,0,0};
    #pragma unroll
    for (int k = 0; k < FM1; k++) {
        float4 wv = *(const float4*)(W + k*64 + col);
        float2 xv = *(const float2*)&sxT[k][n0];
        a0.x += xv.x*wv.x; a0.y += xv.x*wv.y; a0.z += xv.x*wv.z; a0.w += xv.x*wv.w;
        a1.x += xv.y*wv.x; a1.y += xv.y*wv.y; a1.z += xv.y*wv.z; a1.w += xv.y*wv.w;
    }
    *(float4*)(g_u + (base+n0  )*64 + col) = a0;
    *(float4*)(g_u + (base+n0+1)*64 + col) = a1;
    float q0 = a0.x*a0.x + a0.y*a0.y + a0.z*a0.z + a0.w*a0.w;
    float q1 = a1.x*a1.x + a1.y*a1.y + a1.z*a1.z + a1.w*a1.w;
    #pragma unroll
    for (int o = 8; o; o >>= 1) {
        q0 += __shfl_down_sync(0xffffffffu, q0, o, 16);
        q1 += __shfl_down_sync(0xffffffffu, q1, o, 16);
    }
    if (cg == 0) { g_nu[base+n0] = q0; g_nu[base+n0+1] = q1; }
}

// ---------------- alpha + tmp + fused h2/as2/ad2 ----------------
__global__ void k_alpha(const int* __restrict__ A, const float* __restrict__ lin2,
                        const float* __restrict__ as2, const float* __restrict__ ad2)
{
    __shared__ float sv[8*64];
    __shared__ float sy[PAST];
    __shared__ float snv[8];
    __shared__ float sL[8][PAST];
    __shared__ float st[8];
    int b = blockIdx.x >> 3;
    int fb = (blockIdx.x & 7) * 8;
    int p = threadIdx.x;               // 128 threads
    const float* vbase = g_v + (b*FUTURE + fb)*64;
    for (int i = p; i < 512; i += 128) sv[i] = vbase[i];
    sy[p] = g_y1[b*PAST + p];
    if (p < 8) snv[p] = g_nv[b*FUTURE + fb + p];
    __syncthreads();
    float acc[8];
    #pragma unroll
    for (int f = 0; f < 8; f++) acc[f] = 0.f;
    const float4* up4 = (const float4*)(g_u + (b*PAST + p)*64);
    #pragma unroll
    for (int kc = 0; kc < 16; kc++) {
        float4 uq = up4[kc];
        #pragma unroll
        for (int f = 0; f < 8; f++) {
            acc[f] += uq.x*sv[f*64 + kc*4 + 0] + uq.y*sv[f*64 + kc*4 + 1]
                    + uq.z*sv[f*64 + kc*4 + 2] + uq.w*sv[f*64 + kc*4 + 3];
        }
    }
    float nup = g_nu[b*PAST + p];
    const int* Arow = A + p*NB + PAST + fb;
    #pragma unroll
    for (int f = 0; f < 8; f++) {
        float L = 2.f*acc[f] - nup - snv[f];
        if (Arow[f] == 0) L = -1e30f;
        sL[f][p] = L;
    }
    __syncthreads();
    int w = p >> 5, lane = p & 31;
    for (int f = w; f < 8; f += 4) {
        float v0 = sL[f][lane], v1 = sL[f][lane+32], v2 = sL[f][lane+64], v3 = sL[f][lane+96];
        float m = fmaxf(fmaxf(v0, v1), fmaxf(v2, v3));
        #pragma unroll
        for (int o = 16; o; o >>= 1) m = fmaxf(m, __shfl_xor_sync(0xffffffffu, m, o));
        float e0 = __expf(v0 - m), e1 = __expf(v1 - m), e2 = __expf(v2 - m), e3 = __expf(v3 - m);
        float s = e0 + e1 + e2 + e3;
        float a = e0*sy[lane] + e1*sy[lane+32] + e2*sy[lane+64] + e3*sy[lane+96];
        #pragma unroll
        for (int o = 16; o; o >>= 1) {
            s += __shfl_xor_sync(0xffffffffu, s, o);
            a += __shfl_xor_sync(0xffffffffu, a, o);
        }
        if (lane == 0) {
            float tv = a / s;
            g_tmp[b*FUTURE + fb + f] = tv;
            st[f] = tv;
        }
    }
    __syncthreads();
    // fused h2/as2/ad2 for the 8 nodes this block owns
    if (p < 32) {
        int nl = p >> 2, hd = p & 3;
        int gn = b*FUTURE + fb + nl;
        const float* xr = g_xf2 + gn*F;
        float acc2 = 0.f;
        #pragma unroll
        for (int k = 0; k < FM1; k++) acc2 += xr[k]*lin2[k*HEADS + hd];
        acc2 += st[nl]*lin2[FM1*HEADS + hd];
        g_h2[gn*HEADS + hd]  = acc2;
        g_as2[gn*HEADS + hd] = acc2*as2[hd];
        g_ad2[gn*HEADS + hd] = acc2*ad2[hd];
    }
}

// ---------------- GAT2: warp per dst node -> output ----------------
__global__ void k_gat2(float* __restrict__ out, const float* __restrict__ g2b)
{
    int wid = (blockIdx.x*blockDim.x + threadIdx.x) >> 5;
    int lane = threadIdx.x & 31;
    if (wid >= N2) return;
    int n = wid;
    int deg = min(g_cnt2[n], CAP);
    const int* lst = &g_list2[n*CAP];
    float osum = 0.f;
    #pragma unroll
    for (int h = 0; h < HEADS; h++) {
        float ad = g_ad2[n*HEADS + h];
        float s = 0.f, a = 0.f;
        for (int i = lane; i < deg; i += 32) {
            int src = lst[i];
            float e = g_as2[src*HEADS + h] + ad;
            float x = __expf(lrelu(e));
            s += x; a += x*g_h2[src*HEADS + h];
        }
        #pragma unroll
        for (int o = 16; o; o >>= 1) {
            s += __shfl_xor_sync(0xffffffffu, s, o);
            a += __shfl_xor_sync(0xffffffffu, a, o);
        }
        if (lane == 0) {
            float e = g_as2[n*HEADS + h] + ad;
            float x = __expf(lrelu(e));
            s += x; a += x*g_h2[n*HEADS + h];
            osum += a / (s + 1e-16f);
        }
    }
    if (lane == 0) out[n] = 0.25f*osum + g2b[0];
}

// ---------------- launcher ----------------
extern "C" void kernel_launch(void* const* d_in, const int* in_sizes, int n_in,
                              void* d_out, int out_size)
{
    const int*   cat1   = (const int*)  d_in[0];
    const float* num1   = (const float*)d_in[1];
    const int*   cat2   = (const int*)  d_in[2];
    const float* num2   = (const float*)d_in[3];
    const int*   e1     = (const int*)  d_in[4];
    const int*   e2     = (const int*)  d_in[5];
    const int*   A      = (const int*)  d_in[6];
    const float* emb0   = (const float*)d_in[7];
    const float* emb1   = (const float*)d_in[8];
    const float* emb2   = (const float*)d_in[9];
    const float* g1_lin = (const float*)d_in[10];
    const float* g1_as  = (const float*)d_in[11];
    const float* g1_ad  = (const float*)d_in[12];
    const float* g1_b   = (const float*)d_in[13];
    const float* g2_lin = (const float*)d_in[14];
    const float* g2_as  = (const float*)d_in[15];
    const float* g2_ad  = (const float*)d_in[16];
    const float* g2_b   = (const float*)d_in[17];
    const float* W      = (const float*)d_in[18];
    float* out = (float*)d_out;

    k_pre1<<<N1/16, 256>>>(cat1, num1, emb0, emb1, emb2, g1_lin, g1_as, g1_ad);
    k_pre2<<<N2/16, 256>>>(cat2, num2, emb0, emb1, emb2, W);
    k_scatter<<<(E1/4 + E2/4 + 255)/256, 256>>>(e1, e2);
    k_gat1<<<N1, 128>>>();
    k_u<<<N1/32, 256>>>(g1_b, W);
    k_alpha<<<B*8, 128>>>(A, g2_lin, g2_as, g2_ad);
    k_gat2<<<N2*32/256, 256>>>(out, g2_b);
}